// round 15
// baseline (speedup 1.0000x reference)
#include <cuda_runtime.h>
#include <cuda_fp16.h>

// HashGridEncoder2D: L=16, F=2, N=1048576, T=524288. fp16 tables scaled by 4096.
// R15: R13 sort (4096 pts/block, 1024 thr, row-major 32x32 bins) + hashed path
// upgraded to 32B group-of-8 loads (both x-corners in-group 87.5%) with 7-SEL
// value select. Dense levels: 16B quad LDG.

#define NPTS    1048576
#define TSIZE   524288
#define TMASK   (TSIZE - 1)
#define HPRIME  131101
#define QTOTAL  659835                 // sum of res^2 over dense levels 0..11
#define HBASE   663817                 // float2 index where hashed tables start
#define RPTOTAL (QTOTAL + TSIZE)
#define RPBLK   ((RPTOTAL + 1023) / 1024)
#define NBINS   1024
#define SORTBLK 256                    // sort blocks (4096 points each)
#define PPB     4096                   // points per sort block
#define SCALE_F     4096.0f
#define INV_SCALE_F (1.0f / 4096.0f)

// dynamic smem for sort blocks:
// float su[PPB] | float sv[PPB] | int sp[PPB] | int s_cnt[NBINS] | int s_base[NBINS] | int s_wt[32]
#define SMEMSZ (PPB * 12 + NBINS * 8 + 128)

__constant__ int c_res[16] = {16, 22, 30, 42, 58, 80, 111, 153,
                              212, 294, 406, 561, 776, 1072, 1482, 2048};
__constant__ int c_off[16] = {0, 289, 818, 1779, 3628, 7109, 13670, 26214,
                              49930, 95299, 182324, 347973,
                              663817, 1188105, 1712393, 2236681};
__constant__ int c_qoff[12] = {0, 256, 740, 1640, 3404, 6768, 13168,
                               25489, 48898, 93842, 180278, 345114};

// 10.6 MB: dense cell (l,x,y) -> {v00,v01,v10,v11} as 4 half2 (16B aligned).
__device__ __align__(16) __half2 g_qh[(size_t)QTOTAL * 4];
// 8.4 MB: 32B-aligned fp16 mirror of the 4 hashed level tables.
__device__ __align__(32) __half2 g_hh[4 * TSIZE];
// sorted records {u, v, perm-as-int, 0}
__device__ __align__(16) float4 g_uvp[NPTS];

__device__ __forceinline__ __half2 sc_h2(float2 v) {
    return __floats2half2_rn(v.x * SCALE_F, v.y * SCALE_F);
}

__device__ __forceinline__ int bin_of(float px, float py) {
    int kx = min((int)(px * 32.0f), 31);
    int ky = min((int)(py * 32.0f), 31);
    return ky * 32 + kx;
}

// select one of 8 half2 regs with a 7-SEL tree
__device__ __forceinline__ __half2 sel8(const __half2* v, int s) {
    __half2 t0 = (s & 1) ? v[1] : v[0];
    __half2 t1 = (s & 1) ? v[3] : v[2];
    __half2 t2 = (s & 1) ? v[5] : v[4];
    __half2 t3 = (s & 1) ? v[7] : v[6];
    __half2 u0 = (s & 2) ? t1 : t0;
    __half2 u1 = (s & 2) ? t3 : t2;
    return (s & 4) ? u1 : u0;
}

// Fused: blocks [0, SORTBLK) block-local sort; blocks [SORTBLK, ...) repack.
__global__ void __launch_bounds__(1024)
sort_repack_kernel(const float2* __restrict__ uv, const float2* __restrict__ lat)
{
    extern __shared__ char dynsmem[];

    int tid = threadIdx.x;

    if (blockIdx.x < SORTBLK) {
        float* su     = (float*)dynsmem;
        float* sv     = su + PPB;
        int*   sp     = (int*)(sv + PPB);
        int*   s_cnt  = sp + PPB;
        int*   s_base = s_cnt + NBINS;
        int*   s_wt   = s_base + NBINS;

        s_cnt[tid] = 0;
        __syncthreads();

        // phase 1: load 4 points, bin, rank via smem atomics
        const float4* uv4 = (const float4*)uv;
        int base4 = blockIdx.x * (PPB / 2);
        float4 q[2];
        int    bn[4], rk[4];
#pragma unroll
        for (int j = 0; j < 2; j++) {
            q[j] = __ldg(&uv4[base4 + j * 1024 + tid]);
            bn[2 * j]     = bin_of(q[j].x, q[j].y);
            bn[2 * j + 1] = bin_of(q[j].z, q[j].w);
            rk[2 * j]     = atomicAdd(&s_cnt[bn[2 * j]], 1);
            rk[2 * j + 1] = atomicAdd(&s_cnt[bn[2 * j + 1]], 1);
        }
        __syncthreads();

        // phase 2: exclusive scan of 1024 bin counts (shuffle-based)
        int c = s_cnt[tid];
        int lane = tid & 31, wid = tid >> 5;
        int incl = c;
#pragma unroll
        for (int off = 1; off < 32; off <<= 1) {
            int v = __shfl_up_sync(0xffffffffu, incl, off);
            if (lane >= off) incl += v;
        }
        if (lane == 31) s_wt[wid] = incl;
        __syncthreads();
        if (wid == 0) {
            int wv = s_wt[lane];
            int wi = wv;
#pragma unroll
            for (int off = 1; off < 32; off <<= 1) {
                int v = __shfl_up_sync(0xffffffffu, wi, off);
                if (lane >= off) wi += v;
            }
            s_wt[lane] = wi - wv;   // exclusive warp offsets
        }
        __syncthreads();
        s_base[tid] = s_wt[wid] + incl - c;   // exclusive bin base
        __syncthreads();

        // phase 3: scatter records into sorted smem positions
#pragma unroll
        for (int j = 0; j < 2; j++) {
            int n0 = (base4 + j * 1024 + tid) * 2;
            int p0 = s_base[bn[2 * j]] + rk[2 * j];
            int p1 = s_base[bn[2 * j + 1]] + rk[2 * j + 1];
            su[p0] = q[j].x; sv[p0] = q[j].y; sp[p0] = n0;
            su[p1] = q[j].z; sv[p1] = q[j].w; sp[p1] = n0 + 1;
        }
        __syncthreads();

        // phase 4: coalesced write of sorted records
        int gbase = blockIdx.x * PPB;
#pragma unroll
        for (int j = 0; j < 4; j++) {
            int i = j * 1024 + tid;
            g_uvp[gbase + i] = make_float4(su[i], sv[i],
                                           __int_as_float(sp[i]), 0.0f);
        }
        return;
    }

    // ---- repack blocks ----
    int c = (blockIdx.x - SORTBLK) * 1024 + tid;
    if (c >= RPTOTAL) return;

    if (c >= QTOTAL) {
        int base = (c - QTOTAL) * 4;
        __half2 h0 = sc_h2(lat[HBASE + base + 0]);
        __half2 h1 = sc_h2(lat[HBASE + base + 1]);
        __half2 h2 = sc_h2(lat[HBASE + base + 2]);
        __half2 h3 = sc_h2(lat[HBASE + base + 3]);
        float4 v;
        ((__half2*)&v)[0] = h0; ((__half2*)&v)[1] = h1;
        ((__half2*)&v)[2] = h2; ((__half2*)&v)[3] = h3;
        *(float4*)(g_hh + base) = v;
        return;
    }

    int l = 0;
#pragma unroll
    for (int i = 1; i < 12; i++) l += (c >= c_qoff[i]);

    int local = c - c_qoff[l];
    int res   = c_res[l];
    int x     = local / res;
    int y     = local - x * res;
    int base  = c_off[l] + x * res + y;

    __half2 h00 = sc_h2(lat[base]);
    __half2 h01 = sc_h2(lat[base + 1]);
    __half2 h10 = sc_h2(lat[base + res]);
    __half2 h11 = sc_h2(lat[base + res + 1]);

    float4 v;
    ((__half2*)&v)[0] = h00; ((__half2*)&v)[1] = h01;
    ((__half2*)&v)[2] = h10; ((__half2*)&v)[3] = h11;
    *(float4*)(g_qh + (size_t)c * 4) = v;
}

__global__ void __launch_bounds__(256)
hashgrid2d_kernel(float4* __restrict__ out)
{
    __shared__ float2 s_uv[32];
    __shared__ int    s_pn[32];
    __shared__ float4 s_tr[256];

    int tid = threadIdx.x;
    int w   = tid >> 5;          // slot: levels {2w, 2w+1}
    int ln  = tid & 31;
    int n0  = blockIdx.x * 32;

    if (w == 0) {
        float4 q = g_uvp[n0 + ln];
        s_uv[ln] = make_float2(q.x, q.y);
        s_pn[ln] = __float_as_int(q.z);
    }
    __syncthreads();
    float2 p = s_uv[ln];

    float r0, r1, r2, r3;

    if (w < 6) {
        // ---- two dense levels: one 16B quad load each ----
        float rr[4];
#pragma unroll
        for (int k = 0; k < 2; k++) {
            int l   = 2 * w + k;
            int res = c_res[l];

            float fres = (float)res;
            float sx = p.x * fres;
            float sy = p.y * fres;
            float fx = floorf(sx);
            float fy = floorf(sy);
            int   x0 = (int)fx;
            int   y0 = (int)fy;
            float px = sx - fx;
            float py = sy - fy;

            float4 raw = *(const float4*)(g_qh + (size_t)(c_qoff[l] + x0 * res + y0) * 4);
            const __half2* h = (const __half2*)&raw;
            float2 v00 = __half22float2(h[0]);
            float2 v01 = __half22float2(h[1]);
            float2 v10 = __half22float2(h[2]);
            float2 v11 = __half22float2(h[3]);

            float qx = 1.0f - px;
            float qy = 1.0f - py;
            float w00 = qx * qy;
            float w01 = qx * py;
            float w10 = px * qy;
            float w11 = px * py;

            rr[2 * k + 0] = v00.x * w00 + v01.x * w01 + v10.x * w10 + v11.x * w11;
            rr[2 * k + 1] = v00.y * w00 + v01.y * w01 + v10.y * w10 + v11.y * w11;
        }
        r0 = rr[0]; r1 = rr[1]; r2 = rr[2]; r3 = rr[3];
    } else {
        // ---- two hashed levels: 32B group-of-8 loads + 7-SEL value select ----
        float rr[4];
#pragma unroll
        for (int k = 0; k < 2; k++) {
            int l = 12 + (w - 6) * 2 + k;

            float fres = (float)c_res[l];
            float sx = p.x * fres;
            float sy = p.y * fres;
            float fx = floorf(sx);
            float fy = floorf(sy);
            int   x0 = (int)fx;
            int   y0 = (int)fy;
            float px = sx - fx;
            float py = sy - fy;

            float qx = 1.0f - px;
            float qy = 1.0f - py;

            const __half2* H = g_hh + (size_t)(l - 12) * TSIZE;

            int hy0 = y0 * HPRIME;
            int hy1 = hy0 + HPRIME;
            int i0  = (x0 ^ hy0) & TMASK;
            int i1  = (x0 ^ hy1) & TMASK;

            // 32B group loads covering hash slots {g..g+7}
            float g0[8], g1[8];
            asm("ld.global.v8.f32 {%0,%1,%2,%3,%4,%5,%6,%7}, [%8];"
                : "=f"(g0[0]), "=f"(g0[1]), "=f"(g0[2]), "=f"(g0[3]),
                  "=f"(g0[4]), "=f"(g0[5]), "=f"(g0[6]), "=f"(g0[7])
                : "l"((const float*)(H + (i0 & ~7))));
            asm("ld.global.v8.f32 {%0,%1,%2,%3,%4,%5,%6,%7}, [%8];"
                : "=f"(g1[0]), "=f"(g1[1]), "=f"(g1[2]), "=f"(g1[3]),
                  "=f"(g1[4]), "=f"(g1[5]), "=f"(g1[6]), "=f"(g1[7])
                : "l"((const float*)(H + (i1 & ~7))));
            const __half2* v0 = (const __half2*)g0;
            const __half2* v1 = (const __half2*)g1;

            int  d   = ((x0 + 1) ^ x0) & 7;        // 1, 3, or 7
            int  pA0 = i0 & 7, pA1 = i1 & 7;

            __half2 a0 = sel8(v0, pA0);            // x0 corner, row y0
            __half2 a1 = sel8(v1, pA1);            // x0 corner, row y0+1
            __half2 b0 = sel8(v0, pA0 ^ d);        // x0+1 corner (if in-group)
            __half2 b1 = sel8(v1, pA1 ^ d);

            if ((x0 & 7) == 7) {                   // partner outside the group
                int x1 = x0 + 1;
                b0 = H[(x1 ^ hy0) & TMASK];
                b1 = H[(x1 ^ hy1) & TMASK];
            }

            float2 A0 = __half22float2(a0);
            float2 B0 = __half22float2(b0);
            float2 A1 = __half22float2(a1);
            float2 B1 = __half22float2(b1);

            float ex0 = qx * A0.x + px * B0.x;
            float ey0 = qx * A0.y + px * B0.y;
            float ex1 = qx * A1.x + px * B1.x;
            float ey1 = qx * A1.y + px * B1.y;

            rr[2 * k + 0] = qy * ex0 + py * ex1;
            rr[2 * k + 1] = qy * ey0 + py * ey1;
        }
        r0 = rr[0]; r1 = rr[1]; r2 = rr[2]; r3 = rr[3];
    }

    r0 *= INV_SCALE_F; r1 *= INV_SCALE_F; r2 *= INV_SCALE_F; r3 *= INV_SCALE_F;

    // XOR-swizzled transpose; store to each point's ORIGINAL slot (one 128B
    // line per point -> same wavefront count as a coalesced store).
    s_tr[ln * 8 + (w ^ (ln & 7))] = make_float4(r0, r1, r2, r3);
    __syncthreads();

    int jj = tid & 7;
    int ll = tid >> 3;
    int pn = s_pn[ll];
    out[(size_t)pn * 8 + jj] = s_tr[ll * 8 + (jj ^ (ll & 7))];
}

extern "C" void kernel_launch(void* const* d_in, const int* in_sizes, int n_in,
                              void* d_out, int out_size)
{
    const float2* uv  = (const float2*)d_in[0];
    const float2* lat = (const float2*)d_in[1];
    float4*       out = (float4*)d_out;

    // idempotent, not a stream op -> capture-safe
    cudaFuncSetAttribute(sort_repack_kernel,
                         cudaFuncAttributeMaxDynamicSharedMemorySize, SMEMSZ);

    sort_repack_kernel<<<SORTBLK + RPBLK, 1024, SMEMSZ>>>(uv, lat);

    hashgrid2d_kernel<<<NPTS / 32, 256>>>(out);
}

// round 16
// speedup vs baseline: 1.0564x; 1.0564x over previous
#include <cuda_runtime.h>
#include <cuda_fp16.h>

// HashGridEncoder2D: L=16, F=2, N=1048576, T=524288. fp16 tables scaled by 4096.
// R16: R13 main kernel (group-of-4 hashed + sel4, 16B quad dense) unchanged;
// block-local sort upgraded to 64x64 MORTON bins (4096 bins, ~1 pt/bin) so each
// warp's 32 sorted points form a near-square 1/8 x 1/16 uv tile (was a 1/4 x
// 1/32 strip) -> better dense-level line sharing.

#define NPTS    1048576
#define TSIZE   524288
#define TMASK   (TSIZE - 1)
#define HPRIME  131101
#define QTOTAL  659835                 // sum of res^2 over dense levels 0..11
#define HBASE   663817                 // float2 index where hashed tables start
#define RPTOTAL (QTOTAL + TSIZE)
#define RPBLK   ((RPTOTAL + 1023) / 1024)
#define NBINS   4096                   // 64x64 Morton bins
#define SORTBLK 256                    // sort blocks (4096 points each)
#define PPB     4096                   // points per sort block
#define SCALE_F     4096.0f
#define INV_SCALE_F (1.0f / 4096.0f)

// dynamic smem for sort blocks:
// float su[PPB] | float sv[PPB] | int sp[PPB] | int s_cnt[NBINS] | int s_base[NBINS] | int s_wt[32]
#define SMEMSZ (PPB * 12 + NBINS * 8 + 128)

__constant__ int c_res[16] = {16, 22, 30, 42, 58, 80, 111, 153,
                              212, 294, 406, 561, 776, 1072, 1482, 2048};
__constant__ int c_off[16] = {0, 289, 818, 1779, 3628, 7109, 13670, 26214,
                              49930, 95299, 182324, 347973,
                              663817, 1188105, 1712393, 2236681};
__constant__ int c_qoff[12] = {0, 256, 740, 1640, 3404, 6768, 13168,
                               25489, 48898, 93842, 180278, 345114};

// 10.6 MB: dense cell (l,x,y) -> {v00,v01,v10,v11} as 4 half2 (16B aligned).
__device__ __align__(16) __half2 g_qh[(size_t)QTOTAL * 4];
// 8.4 MB: 16B-aligned fp16 mirror of the 4 hashed level tables.
__device__ __align__(16) __half2 g_hh[4 * TSIZE];
// sorted records {u, v, perm-as-int, 0}
__device__ __align__(16) float4 g_uvp[NPTS];

__device__ __forceinline__ __half2 sc_h2(float2 v) {
    return __floats2half2_rn(v.x * SCALE_F, v.y * SCALE_F);
}

// Morton (Z-order) bin index over a 64x64 grid
__device__ __forceinline__ int bin_of(float px, float py) {
    unsigned kx = min((int)(px * 64.0f), 63);
    unsigned ky = min((int)(py * 64.0f), 63);
    kx = (kx | (kx << 4)) & 0x0F0F; kx = (kx | (kx << 2)) & 0x3333;
    kx = (kx | (kx << 1)) & 0x5555;
    ky = (ky | (ky << 4)) & 0x0F0F; ky = (ky | (ky << 2)) & 0x3333;
    ky = (ky | (ky << 1)) & 0x5555;
    return (int)(kx | (ky << 1));
}

// select one of 4 half2 regs with a 3-SEL tree
__device__ __forceinline__ __half2 sel4(const __half2* v, int s) {
    __half2 t0 = (s & 1) ? v[1] : v[0];
    __half2 t1 = (s & 1) ? v[3] : v[2];
    return (s & 2) ? t1 : t0;
}

// Fused: blocks [0, SORTBLK) block-local sort; blocks [SORTBLK, ...) repack.
__global__ void __launch_bounds__(1024)
sort_repack_kernel(const float2* __restrict__ uv, const float2* __restrict__ lat)
{
    extern __shared__ char dynsmem[];

    int tid = threadIdx.x;

    if (blockIdx.x < SORTBLK) {
        float* su     = (float*)dynsmem;
        float* sv     = su + PPB;
        int*   sp     = (int*)(sv + PPB);
        int*   s_cnt  = sp + PPB;
        int*   s_base = s_cnt + NBINS;
        int*   s_wt   = s_base + NBINS;

#pragma unroll
        for (int i = 0; i < 4; i++) s_cnt[tid + i * 1024] = 0;
        __syncthreads();

        // phase 1: load 4 points, bin, rank via smem atomics
        const float4* uv4 = (const float4*)uv;
        int base4 = blockIdx.x * (PPB / 2);
        float4 q[2];
        int    bn[4], rk[4];
#pragma unroll
        for (int j = 0; j < 2; j++) {
            q[j] = __ldg(&uv4[base4 + j * 1024 + tid]);
            bn[2 * j]     = bin_of(q[j].x, q[j].y);
            bn[2 * j + 1] = bin_of(q[j].z, q[j].w);
            rk[2 * j]     = atomicAdd(&s_cnt[bn[2 * j]], 1);
            rk[2 * j + 1] = atomicAdd(&s_cnt[bn[2 * j + 1]], 1);
        }
        __syncthreads();

        // phase 2: exclusive scan of 4096 bins, 4 per thread (shuffle-based)
        int c0 = s_cnt[4 * tid + 0];
        int c1 = s_cnt[4 * tid + 1];
        int c2 = s_cnt[4 * tid + 2];
        int c3 = s_cnt[4 * tid + 3];
        int s  = c0 + c1 + c2 + c3;
        int lane = tid & 31, wid = tid >> 5;
        int incl = s;
#pragma unroll
        for (int off = 1; off < 32; off <<= 1) {
            int v = __shfl_up_sync(0xffffffffu, incl, off);
            if (lane >= off) incl += v;
        }
        if (lane == 31) s_wt[wid] = incl;
        __syncthreads();
        if (wid == 0) {
            int wv = s_wt[lane];
            int wi = wv;
#pragma unroll
            for (int off = 1; off < 32; off <<= 1) {
                int v = __shfl_up_sync(0xffffffffu, wi, off);
                if (lane >= off) wi += v;
            }
            s_wt[lane] = wi - wv;   // exclusive warp offsets
        }
        __syncthreads();
        int excl = s_wt[wid] + incl - s;
        s_base[4 * tid + 0] = excl;
        s_base[4 * tid + 1] = excl + c0;
        s_base[4 * tid + 2] = excl + c0 + c1;
        s_base[4 * tid + 3] = excl + c0 + c1 + c2;
        __syncthreads();

        // phase 3: scatter records into sorted smem positions
#pragma unroll
        for (int j = 0; j < 2; j++) {
            int n0 = (base4 + j * 1024 + tid) * 2;
            int p0 = s_base[bn[2 * j]] + rk[2 * j];
            int p1 = s_base[bn[2 * j + 1]] + rk[2 * j + 1];
            su[p0] = q[j].x; sv[p0] = q[j].y; sp[p0] = n0;
            su[p1] = q[j].z; sv[p1] = q[j].w; sp[p1] = n0 + 1;
        }
        __syncthreads();

        // phase 4: coalesced write of sorted records
        int gbase = blockIdx.x * PPB;
#pragma unroll
        for (int j = 0; j < 4; j++) {
            int i = j * 1024 + tid;
            g_uvp[gbase + i] = make_float4(su[i], sv[i],
                                           __int_as_float(sp[i]), 0.0f);
        }
        return;
    }

    // ---- repack blocks ----
    int c = (blockIdx.x - SORTBLK) * 1024 + tid;
    if (c >= RPTOTAL) return;

    if (c >= QTOTAL) {
        int base = (c - QTOTAL) * 4;
        __half2 h0 = sc_h2(lat[HBASE + base + 0]);
        __half2 h1 = sc_h2(lat[HBASE + base + 1]);
        __half2 h2 = sc_h2(lat[HBASE + base + 2]);
        __half2 h3 = sc_h2(lat[HBASE + base + 3]);
        float4 v;
        ((__half2*)&v)[0] = h0; ((__half2*)&v)[1] = h1;
        ((__half2*)&v)[2] = h2; ((__half2*)&v)[3] = h3;
        *(float4*)(g_hh + base) = v;
        return;
    }

    int l = 0;
#pragma unroll
    for (int i = 1; i < 12; i++) l += (c >= c_qoff[i]);

    int local = c - c_qoff[l];
    int res   = c_res[l];
    int x     = local / res;
    int y     = local - x * res;
    int base  = c_off[l] + x * res + y;

    __half2 h00 = sc_h2(lat[base]);
    __half2 h01 = sc_h2(lat[base + 1]);
    __half2 h10 = sc_h2(lat[base + res]);
    __half2 h11 = sc_h2(lat[base + res + 1]);

    float4 v;
    ((__half2*)&v)[0] = h00; ((__half2*)&v)[1] = h01;
    ((__half2*)&v)[2] = h10; ((__half2*)&v)[3] = h11;
    *(float4*)(g_qh + (size_t)c * 4) = v;
}

__global__ void __launch_bounds__(256)
hashgrid2d_kernel(float4* __restrict__ out)
{
    __shared__ float2 s_uv[32];
    __shared__ int    s_pn[32];
    __shared__ float4 s_tr[256];

    int tid = threadIdx.x;
    int w   = tid >> 5;          // slot: levels {2w, 2w+1}
    int ln  = tid & 31;
    int n0  = blockIdx.x * 32;

    if (w == 0) {
        float4 q = g_uvp[n0 + ln];
        s_uv[ln] = make_float2(q.x, q.y);
        s_pn[ln] = __float_as_int(q.z);
    }
    __syncthreads();
    float2 p = s_uv[ln];

    float r0, r1, r2, r3;

    if (w < 6) {
        // ---- two dense levels: one 16B quad load each ----
        float rr[4];
#pragma unroll
        for (int k = 0; k < 2; k++) {
            int l   = 2 * w + k;
            int res = c_res[l];

            float fres = (float)res;
            float sx = p.x * fres;
            float sy = p.y * fres;
            float fx = floorf(sx);
            float fy = floorf(sy);
            int   x0 = (int)fx;
            int   y0 = (int)fy;
            float px = sx - fx;
            float py = sy - fy;

            float4 raw = *(const float4*)(g_qh + (size_t)(c_qoff[l] + x0 * res + y0) * 4);
            const __half2* h = (const __half2*)&raw;
            float2 v00 = __half22float2(h[0]);
            float2 v01 = __half22float2(h[1]);
            float2 v10 = __half22float2(h[2]);
            float2 v11 = __half22float2(h[3]);

            float qx = 1.0f - px;
            float qy = 1.0f - py;
            float w00 = qx * qy;
            float w01 = qx * py;
            float w10 = px * qy;
            float w11 = px * py;

            rr[2 * k + 0] = v00.x * w00 + v01.x * w01 + v10.x * w10 + v11.x * w11;
            rr[2 * k + 1] = v00.y * w00 + v01.y * w01 + v10.y * w10 + v11.y * w11;
        }
        r0 = rr[0]; r1 = rr[1]; r2 = rr[2]; r3 = rr[3];
    } else {
        // ---- two hashed levels: group-of-4 loads + direct value select ----
        float rr[4];
#pragma unroll
        for (int k = 0; k < 2; k++) {
            int l = 12 + (w - 6) * 2 + k;

            float fres = (float)c_res[l];
            float sx = p.x * fres;
            float sy = p.y * fres;
            float fx = floorf(sx);
            float fy = floorf(sy);
            int   x0 = (int)fx;
            int   y0 = (int)fy;
            float px = sx - fx;
            float py = sy - fy;

            float qx = 1.0f - px;
            float qy = 1.0f - py;

            const __half2* H = g_hh + (size_t)(l - 12) * TSIZE;

            int hy0 = y0 * HPRIME;
            int hy1 = hy0 + HPRIME;
            int i0  = (x0 ^ hy0) & TMASK;
            int i1  = (x0 ^ hy1) & TMASK;

            float4 raw0 = *(const float4*)(H + (i0 & ~3));
            float4 raw1 = *(const float4*)(H + (i1 & ~3));
            const __half2* v0 = (const __half2*)&raw0;
            const __half2* v1 = (const __half2*)&raw1;

            int  d   = ((x0 + 1) ^ x0) & 3;        // 1 or 3
            int  pA0 = i0 & 3, pA1 = i1 & 3;

            __half2 a0 = sel4(v0, pA0);            // x0 corner, row y0
            __half2 a1 = sel4(v1, pA1);            // x0 corner, row y0+1
            __half2 b0 = sel4(v0, pA0 ^ d);        // x0+1 corner (if in-group)
            __half2 b1 = sel4(v1, pA1 ^ d);

            if ((x0 & 3) == 3) {                   // partner outside the group
                int x1 = x0 + 1;
                b0 = H[(x1 ^ hy0) & TMASK];
                b1 = H[(x1 ^ hy1) & TMASK];
            }

            float2 A0 = __half22float2(a0);
            float2 B0 = __half22float2(b0);
            float2 A1 = __half22float2(a1);
            float2 B1 = __half22float2(b1);

            float ex0 = qx * A0.x + px * B0.x;
            float ey0 = qx * A0.y + px * B0.y;
            float ex1 = qx * A1.x + px * B1.x;
            float ey1 = qx * A1.y + px * B1.y;

            rr[2 * k + 0] = qy * ex0 + py * ex1;
            rr[2 * k + 1] = qy * ey0 + py * ey1;
        }
        r0 = rr[0]; r1 = rr[1]; r2 = rr[2]; r3 = rr[3];
    }

    r0 *= INV_SCALE_F; r1 *= INV_SCALE_F; r2 *= INV_SCALE_F; r3 *= INV_SCALE_F;

    // XOR-swizzled transpose; store to each point's ORIGINAL slot (one 128B
    // line per point -> same wavefront count as a coalesced store).
    s_tr[ln * 8 + (w ^ (ln & 7))] = make_float4(r0, r1, r2, r3);
    __syncthreads();

    int jj = tid & 7;
    int ll = tid >> 3;
    int pn = s_pn[ll];
    out[(size_t)pn * 8 + jj] = s_tr[ll * 8 + (jj ^ (ll & 7))];
}

extern "C" void kernel_launch(void* const* d_in, const int* in_sizes, int n_in,
                              void* d_out, int out_size)
{
    const float2* uv  = (const float2*)d_in[0];
    const float2* lat = (const float2*)d_in[1];
    float4*       out = (float4*)d_out;

    // idempotent, not a stream op -> capture-safe
    cudaFuncSetAttribute(sort_repack_kernel,
                         cudaFuncAttributeMaxDynamicSharedMemorySize, SMEMSZ);

    sort_repack_kernel<<<SORTBLK + RPBLK, 1024, SMEMSZ>>>(uv, lat);

    hashgrid2d_kernel<<<NPTS / 32, 256>>>(out);
}